// round 3
// baseline (speedup 1.0000x reference)
#include <cuda_runtime.h>
#include <math.h>

#define NC 4096
#define NF 16384
#define CC 512
#define CF 256
#define CO 256
#define KTOT 768

// scratch (device globals: allocation-free)
__device__ float g_G[NC * CO];     // coarse_features @ Wc^T   (4 MB, L2-resident)
__device__ float g_F[NF * CO];     // fine_features @ Wf^T     (16 MB)
__device__ int   g_idx[NF * 3];
__device__ float g_w[NF * 3];

// ---------------------------------------------------------------------------
// Kernel 1: kNN (k=3) with ambiguity resolution. One thread per fine point;
// all coarse points (pos + |c|^2) staged in shared memory as float4.
// Primary distance mirrors the reference's fp32 expansion:
//   d2 = (|f|^2 + |c|^2) - 2*(f.c)
// We keep the top-4; if the rank-3/4 gap is below a cancellation-noise
// threshold, the boundary is re-resolved with an exact fp64 direct-form
// distance (true ordering).
// ---------------------------------------------------------------------------
__global__ void knn_kernel(const float* __restrict__ cpos,
                           const float* __restrict__ fpos,
                           int* __restrict__ idx_out,
                           float* __restrict__ w_out) {
    extern __shared__ float4 sc[];
    for (int i = threadIdx.x; i < NC; i += blockDim.x) {
        float x = cpos[3 * i], y = cpos[3 * i + 1], z = cpos[3 * i + 2];
        float cc = __fadd_rn(__fadd_rn(__fmul_rn(x, x), __fmul_rn(y, y)),
                             __fmul_rn(z, z));
        sc[i] = make_float4(x, y, z, cc);
    }
    __syncthreads();

    int n = blockIdx.x * blockDim.x + threadIdx.x;
    float fx = fpos[3 * n], fy = fpos[3 * n + 1], fz = fpos[3 * n + 2];
    float ff = __fadd_rn(__fadd_rn(__fmul_rn(fx, fx), __fmul_rn(fy, fy)),
                         __fmul_rn(fz, fz));

    float b0 = 3.4e38f, b1 = 3.4e38f, b2 = 3.4e38f, b3 = 3.4e38f;
    int   i0 = 0, i1 = 0, i2 = 0, i3 = 0;

#pragma unroll 4
    for (int j = 0; j < NC; j++) {
        float4 c = sc[j];
        float dot = __fmaf_rn(fz, c.z, __fmaf_rn(fy, c.y, __fmul_rn(fx, c.x)));
        float d = __fadd_rn(__fadd_rn(ff, c.w), __fmul_rn(-2.0f, dot));
        if (d < b3) {
            if (d < b2) {
                b3 = b2; i3 = i2;
                if (d < b1) {
                    b2 = b1; i2 = i1;
                    if (d < b0) { b1 = b0; i1 = i0; b0 = d; i0 = j; }
                    else        { b1 = d;  i1 = j; }
                } else {
                    b2 = d; i2 = j;
                }
            } else {
                b3 = d; i3 = j;
            }
        }
    }

    // Ambiguous rank-3/4 boundary: resolve with exact fp64 direct-form d^2.
    if (b3 - b2 < 1e-5f) {
        double dax = (double)fx - (double)cpos[3 * i2];
        double day = (double)fy - (double)cpos[3 * i2 + 1];
        double daz = (double)fz - (double)cpos[3 * i2 + 2];
        double da = dax * dax + day * day + daz * daz;
        double dbx = (double)fx - (double)cpos[3 * i3];
        double dby = (double)fy - (double)cpos[3 * i3 + 1];
        double dbz = (double)fz - (double)cpos[3 * i3 + 2];
        double db = dbx * dbx + dby * dby + dbz * dbz;
        if (db < da || (db == da && i3 < i2)) { i2 = i3; b2 = b3; }
    }

    float w0 = 1.0f / fmaxf(b0, 1e-16f);
    float w1 = 1.0f / fmaxf(b1, 1e-16f);
    float w2 = 1.0f / fmaxf(b2, 1e-16f);
    float inv = 1.0f / (w0 + w1 + w2);

    idx_out[3 * n]     = i0;
    idx_out[3 * n + 1] = i1;
    idx_out[3 * n + 2] = i2;
    w_out[3 * n]     = w0 * inv;
    w_out[3 * n + 1] = w1 * inv;
    w_out[3 * n + 2] = w2 * inv;
}

// ---------------------------------------------------------------------------
// Kernel 2/3: SGEMM  C[M,N] = A[M,K] * B[N,K]^T  (fp32 SIMT, 64x64x16 tiles,
// 256 threads, 4x4 microtile). M,N,K all multiples of tile dims (no guards).
// ---------------------------------------------------------------------------
#define BM 64
#define BN 64
#define BK 16

__global__ __launch_bounds__(256) void sgemm_nt(const float* __restrict__ A, int lda,
                                                const float* __restrict__ B, int ldb,
                                                float* __restrict__ C, int ldc, int K) {
    __shared__ float As[BK][BM];
    __shared__ float Bs[BK][BN];

    int tid = threadIdx.x;
    int tx = tid & 15;        // 0..15 -> n microtile
    int ty = tid >> 4;        // 0..15 -> m microtile
    int m0 = blockIdx.y * BM;
    int n0 = blockIdx.x * BN;

    int lrow  = tid >> 2;          // 0..63
    int lcol4 = (tid & 3) * 4;     // 0,4,8,12

    float acc[4][4] = {};

    for (int k0 = 0; k0 < K; k0 += BK) {
        float4 av = *(const float4*)(A + (size_t)(m0 + lrow) * lda + k0 + lcol4);
        float4 bv = *(const float4*)(B + (size_t)(n0 + lrow) * ldb + k0 + lcol4);
        As[lcol4 + 0][lrow] = av.x; As[lcol4 + 1][lrow] = av.y;
        As[lcol4 + 2][lrow] = av.z; As[lcol4 + 3][lrow] = av.w;
        Bs[lcol4 + 0][lrow] = bv.x; Bs[lcol4 + 1][lrow] = bv.y;
        Bs[lcol4 + 2][lrow] = bv.z; Bs[lcol4 + 3][lrow] = bv.w;
        __syncthreads();

#pragma unroll
        for (int kk = 0; kk < BK; kk++) {
            float4 a = *(const float4*)&As[kk][ty * 4];
            float4 b = *(const float4*)&Bs[kk][tx * 4];
            acc[0][0] += a.x * b.x; acc[0][1] += a.x * b.y;
            acc[0][2] += a.x * b.z; acc[0][3] += a.x * b.w;
            acc[1][0] += a.y * b.x; acc[1][1] += a.y * b.y;
            acc[1][2] += a.y * b.z; acc[1][3] += a.y * b.w;
            acc[2][0] += a.z * b.x; acc[2][1] += a.z * b.y;
            acc[2][2] += a.z * b.z; acc[2][3] += a.z * b.w;
            acc[3][0] += a.w * b.x; acc[3][1] += a.w * b.y;
            acc[3][2] += a.w * b.z; acc[3][3] += a.w * b.w;
        }
        __syncthreads();
    }

#pragma unroll
    for (int i = 0; i < 4; i++) {
        float4 v = make_float4(acc[i][0], acc[i][1], acc[i][2], acc[i][3]);
        *(float4*)(C + (size_t)(m0 + ty * 4 + i) * ldc + n0 + tx * 4) = v;
    }
}

// ---------------------------------------------------------------------------
// Kernel 4: epilogue — gather 3 rows of G, add F row + bias, ReLU, LayerNorm.
// One 256-thread block per fine row.
// ---------------------------------------------------------------------------
__global__ __launch_bounds__(CO) void epilogue_kernel(
    const float* __restrict__ G, const float* __restrict__ Fm,
    const int* __restrict__ idx, const float* __restrict__ w,
    const float* __restrict__ bias, const float* __restrict__ gamma,
    const float* __restrict__ beta, float* __restrict__ out) {

    int n = blockIdx.x;
    int o = threadIdx.x;

    int i0 = idx[3 * n], i1 = idx[3 * n + 1], i2 = idx[3 * n + 2];
    float w0 = w[3 * n], w1 = w[3 * n + 1], w2 = w[3 * n + 2];

    float h = w0 * G[(size_t)i0 * CO + o]
            + w1 * G[(size_t)i1 * CO + o]
            + w2 * G[(size_t)i2 * CO + o]
            + Fm[(size_t)n * CO + o] + bias[o];
    h = fmaxf(h, 0.0f);

    // block reduce sum(h), sum(h^2)
    float s1 = h, s2 = h * h;
#pragma unroll
    for (int off = 16; off; off >>= 1) {
        s1 += __shfl_xor_sync(0xffffffffu, s1, off);
        s2 += __shfl_xor_sync(0xffffffffu, s2, off);
    }
    __shared__ float p1[8], p2[8], stats[2];
    int warp = o >> 5, lane = o & 31;
    if (lane == 0) { p1[warp] = s1; p2[warp] = s2; }
    __syncthreads();
    if (o == 0) {
        float t1 = 0.f, t2 = 0.f;
#pragma unroll
        for (int i = 0; i < 8; i++) { t1 += p1[i]; t2 += p2[i]; }
        float mu  = t1 * (1.0f / CO);
        float var = t2 * (1.0f / CO) - mu * mu;
        stats[0] = mu;
        stats[1] = rsqrtf(var + 1e-5f);
    }
    __syncthreads();
    float mu = stats[0], rinv = stats[1];
    out[(size_t)n * CO + o] = gamma[o] * (h - mu) * rinv + beta[o];
}

// ---------------------------------------------------------------------------
extern "C" void kernel_launch(void* const* d_in, const int* in_sizes, int n_in,
                              void* d_out, int out_size) {
    const float* cfeat = (const float*)d_in[0];  // [4096, 512]
    const float* cpos  = (const float*)d_in[1];  // [4096, 3]
    const float* ffeat = (const float*)d_in[2];  // [16384, 256]
    const float* fpos  = (const float*)d_in[3];  // [16384, 3]
    const float* W     = (const float*)d_in[4];  // [256, 768]
    const float* bias  = (const float*)d_in[5];  // [256]
    const float* gamma = (const float*)d_in[6];  // [256]
    const float* beta  = (const float*)d_in[7];  // [256]
    float* out = (float*)d_out;

    float *G, *Fm, *wp;
    int* idxp;
    cudaGetSymbolAddress((void**)&G,    g_G);
    cudaGetSymbolAddress((void**)&Fm,   g_F);
    cudaGetSymbolAddress((void**)&idxp, g_idx);
    cudaGetSymbolAddress((void**)&wp,   g_w);

    // kNN: 64 KB dynamic shared (all 4096 coarse points as float4)
    cudaFuncSetAttribute(knn_kernel, cudaFuncAttributeMaxDynamicSharedMemorySize,
                         NC * (int)sizeof(float4));
    knn_kernel<<<NF / 128, 128, NC * sizeof(float4)>>>(cpos, fpos, idxp, wp);

    // G = coarse_features @ Wc^T   (Wc = W[:, :512])
    {
        dim3 grid(CO / BN, NC / BM);
        sgemm_nt<<<grid, 256>>>(cfeat, CC, W, KTOT, G, CO, CC);
    }
    // F = fine_features @ Wf^T     (Wf = W[:, 512:768])
    {
        dim3 grid(CO / BN, NF / BM);
        sgemm_nt<<<grid, 256>>>(ffeat, CF, W + CC, KTOT, Fm, CO, CF);
    }

    epilogue_kernel<<<NF, CO>>>(G, Fm, idxp, wp, bias, gamma, beta, out);
}